// round 12
// baseline (speedup 1.0000x reference)
#include <cuda_runtime.h>
#include <cstdint>
#include <math.h>

#define BATCH   32768
#define NBLK    16
#define KD      32
#define NSTATE  (NBLK*KD)    // 512
#define INDIM   64
#define DT_C    0.05f
#define TAU_EPS 1e-6f
#define MTILE   128
#define TPB     128
#define PTPB    256

// smem float offsets; ST=36 row stride
#define ST      36
#define SBUFA   0                    // y_{j-1}/net0 -> actA (128x36)
#define SBUFB   (SBUFA + 128*ST)     // y_j -> actR          (128x36)
#define SWF     (SBUFB + 128*ST)     // 32x36 each
#define SWR     (SWF  + 32*ST)
#define SEL     (SWR  + 32*ST)
#define SELR    (SEL  + 32*ST)
#define SBF     (SELR + 32*ST)
#define SBR     (SBF + 32)
#define SSIT    (SBR + 32)
#define SM_FLOATS (SSIT + 32)
#define SMEM_BYTES (SM_FLOATS*4)

// K-column permutation: col c -> p(c)
#define PERM(c) ((((c)&3)<<3) + (((c)>>3)<<1) + (((c)>>2)&1))

__device__ float g_buf0[BATCH*NSTATE];
__device__ float g_buf1[BATCH*NSTATE];
__device__ float g_net0[BATCH*KD];

__device__ __forceinline__ float fast_tanh(float x) {
    float r; asm("tanh.approx.f32 %0, %1;" : "=f"(r) : "f"(x)); return r;
}
__device__ __forceinline__ float to_tf32f(float f) {
    uint32_t r; asm("cvt.rna.tf32.f32 %0, %1;" : "=r"(r) : "f"(f));
    return __uint_as_float(r);
}
__device__ __forceinline__ void mma8(float c[4], float a0, float a1, float a2,
                                     float a3, float b0, float b1) {
    asm volatile(
        "mma.sync.aligned.m16n8k8.row.col.f32.tf32.tf32.f32 "
        "{%0,%1,%2,%3}, {%4,%5,%6,%7}, {%8,%9}, {%0,%1,%2,%3};"
        : "+f"(c[0]), "+f"(c[1]), "+f"(c[2]), "+f"(c[3])
        : "r"(__float_as_uint(a0)), "r"(__float_as_uint(a1)),
          "r"(__float_as_uint(a2)), "r"(__float_as_uint(a3)),
          "r"(__float_as_uint(b0)), "r"(__float_as_uint(b1)));
}

// stage one 32-float row (tf32-rounded) into permuted layout
__device__ __forceinline__ void stage_row_perm(float* __restrict__ dstrow,
                                               const float4* __restrict__ src) {
    float4 f[8];
#pragma unroll
    for (int q = 0; q < 8; ++q) {
        float4 v = src[q];
        f[q] = make_float4(to_tf32f(v.x), to_tf32f(v.y), to_tf32f(v.z), to_tf32f(v.w));
    }
    float4* d4 = reinterpret_cast<float4*>(dstrow);
    d4[0] = make_float4(f[0].x, f[1].x, f[2].x, f[3].x);
    d4[1] = make_float4(f[4].x, f[5].x, f[6].x, f[7].x);
    d4[2] = make_float4(f[0].y, f[1].y, f[2].y, f[3].y);
    d4[3] = make_float4(f[4].y, f[5].y, f[6].y, f[7].y);
    d4[4] = make_float4(f[0].z, f[1].z, f[2].z, f[3].z);
    d4[5] = make_float4(f[4].z, f[5].z, f[6].z, f[7].z);
    d4[6] = make_float4(f[0].w, f[1].w, f[2].w, f[3].w);
    d4[7] = make_float4(f[4].w, f[5].w, f[6].w, f[7].w);
}

// C[2][4][4] += A(rows rowbase..+31, permuted) @ W^T (permuted)
__device__ __forceinline__ void gemm32p(const float* __restrict__ sA, int rowbase,
                                        const float* __restrict__ sW,
                                        float C[2][4][4], int g, int tig) {
    float B[4][8];
#pragma unroll
    for (int nt = 0; nt < 4; ++nt) {
        const float4* wr = reinterpret_cast<const float4*>(sW + (nt*8+g)*ST + tig*8);
        float4 w0 = wr[0], w1 = wr[1];
        B[nt][0]=w0.x; B[nt][1]=w0.y; B[nt][2]=w0.z; B[nt][3]=w0.w;
        B[nt][4]=w1.x; B[nt][5]=w1.y; B[nt][6]=w1.z; B[nt][7]=w1.w;
    }
#pragma unroll
    for (int t = 0; t < 2; ++t) {
        int rb = rowbase + 16*t;
        const float4* al = reinterpret_cast<const float4*>(sA + (rb+g)*ST + tig*8);
        const float4* ah = reinterpret_cast<const float4*>(sA + (rb+g+8)*ST + tig*8);
        float4 l0 = al[0], l1 = al[1], h0 = ah[0], h1 = ah[1];
        float lo[8] = {l0.x,l0.y,l0.z,l0.w,l1.x,l1.y,l1.z,l1.w};
        float hi[8] = {h0.x,h0.y,h0.z,h0.w,h1.x,h1.y,h1.z,h1.w};
#pragma unroll
        for (int ks = 0; ks < 4; ++ks)
#pragma unroll
            for (int nt = 0; nt < 4; ++nt)
                mma8(C[t][nt], lo[2*ks], hi[2*ks], lo[2*ks+1], hi[2*ks+1],
                     B[nt][2*ks], B[nt][2*ks+1]);
    }
}

// ---------------- Kernel A: net0 precompute ----------------
__global__ __launch_bounds__(PTPB) void ltcn_precompute(
    const float* __restrict__ u_t, const float* __restrict__ W_in,
    const float* __restrict__ b_in)
{
    __shared__ __align__(16) float sWin[KD*INDIM];
    __shared__ float sbin[KD];
    int tid = threadIdx.x;
    for (int i = tid; i < KD*INDIM; i += PTPB) sWin[i] = W_in[i];
    if (tid < KD) sbin[tid] = b_in[tid];
    __syncthreads();

    int b = blockIdx.x * PTPB + tid;
    if (b >= BATCH) return;

    float u[INDIM];
    const float4* up = reinterpret_cast<const float4*>(u_t + (size_t)b * INDIM);
#pragma unroll
    for (int i = 0; i < INDIM/4; ++i) {
        float4 t = up[i];
        u[4*i+0]=t.x; u[4*i+1]=t.y; u[4*i+2]=t.z; u[4*i+3]=t.w;
    }
    float n0[KD];
#pragma unroll 4
    for (int l = 0; l < KD; ++l) {
        float acc = sbin[l];
        const float4* wr = reinterpret_cast<const float4*>(sWin + l*INDIM);
#pragma unroll
        for (int i = 0; i < INDIM/4; ++i) {
            float4 w = wr[i];
            acc = fmaf(w.x, u[4*i+0], acc);
            acc = fmaf(w.y, u[4*i+1], acc);
            acc = fmaf(w.z, u[4*i+2], acc);
            acc = fmaf(w.w, u[4*i+3], acc);
        }
        n0[l] = fast_tanh(acc);
    }
    float4* op = reinterpret_cast<float4*>(g_net0 + (size_t)b * KD);
#pragma unroll
    for (int i = 0; i < 8; ++i)
        op[i] = make_float4(n0[4*i], n0[4*i+1], n0[4*i+2], n0[4*i+3]);
}

// ---------------- Step kernel ----------------
__global__ __launch_bounds__(TPB, 4) void ltcn_step_mma(
    const float* __restrict__ src, float* __restrict__ dst,
    const float* __restrict__ W_fwd, const float* __restrict__ b_fwd,
    const float* __restrict__ W_rec, const float* __restrict__ b_rec,
    const float* __restrict__ E_l,   const float* __restrict__ E_lr,
    const float* __restrict__ tau_raw, const int* __restrict__ n_steps, int s)
{
    extern __shared__ __align__(16) float smf[];
    const int tid  = threadIdx.x;
    const int wid  = tid >> 5;
    const int lane = tid & 31;
    const int g    = lane >> 2;
    const int tig  = lane & 3;
    const int j    = blockIdx.y;
    const int gRow = blockIdx.x * MTILE;

    const float* ysl = src + (size_t)gRow*NSTATE + (size_t)j*KD;
    float*       odl = dst + (size_t)gRow*NSTATE + (size_t)j*KD;

    if (s >= *n_steps) {   // passthrough
        const float4* in4 = reinterpret_cast<const float4*>(ysl + (size_t)tid*NSTATE);
        float4*       o4  = reinterpret_cast<float4*>(odl + (size_t)tid*NSTATE);
#pragma unroll
        for (int i = 0; i < 8; ++i) o4[i] = in4[i];
        return;
    }

    // ---- stage weights: thread = (mat, row), permuted rows ----
    {
        const int mat = tid >> 5, row = lane;
        const float* wsrc = nullptr;
        float* wdst = nullptr;
        if (mat == 0) { if (j > 0) { wsrc = W_fwd + (size_t)(j-1)*KD*KD + row*KD; wdst = smf + SWF + row*ST; } }
        else if (mat == 1) { wsrc = W_rec + (size_t)j*KD*KD + row*KD; wdst = smf + SWR + row*ST; }
        else if (mat == 2) { wsrc = E_l  + (size_t)j*KD*KD + row*KD; wdst = smf + SEL + row*ST; }
        else               { wsrc = E_lr + (size_t)j*KD*KD + row*KD; wdst = smf + SELR + row*ST; }
        if (wsrc) stage_row_perm(wdst, reinterpret_cast<const float4*>(wsrc));
    }
    // ---- stage activations: thread = row ----
    stage_row_perm(smf + SBUFB + tid*ST,
                   reinterpret_cast<const float4*>(ysl + (size_t)tid*NSTATE));
    if (j > 0) {
        stage_row_perm(smf + SBUFA + tid*ST,
                       reinterpret_cast<const float4*>(
                           src + (size_t)(gRow+tid)*NSTATE + (size_t)(j-1)*KD));
    } else {
        stage_row_perm(smf + SBUFA + tid*ST,
                       reinterpret_cast<const float4*>(g_net0 + (size_t)(gRow+tid)*KD));
    }
    if (tid < KD) {
        smf[SBR + tid] = b_rec[j*KD + tid];
        if (j > 0) smf[SBF + tid] = b_fwd[(j-1)*KD + tid];
        float t  = tau_raw[j*KD + tid];
        float sp = (t > 20.f) ? t : log1pf(expf(t));
        smf[SSIT + tid] = 1.0f / (sp + TAU_EPS);
    }
    __syncthreads();

    const int rowbase = wid * 32;

    // ---- GEMM P (j>0): bufA(y_{j-1}) @ Wf^T -> actA back into bufA ----
    if (j > 0) {
        float C[2][4][4];
#pragma unroll
        for (int t=0;t<2;++t)
#pragma unroll
            for (int nt=0;nt<4;++nt)
#pragma unroll
                for (int q=0;q<4;++q) C[t][nt][q] = 0.f;
        gemm32p(smf + SBUFA, rowbase, smf + SWF, C, g, tig);
        __syncwarp();
#pragma unroll
        for (int t=0;t<2;++t)
#pragma unroll
            for (int nt=0;nt<4;++nt) {
                int col = nt*8 + 2*tig;
                float b0 = smf[SBF+col], b1 = smf[SBF+col+1];
#pragma unroll
                for (int h=0;h<2;++h) {
                    int r = rowbase + 16*t + g + 8*h;
                    smf[SBUFA + r*ST + PERM(col)]   =
                        to_tf32f(fast_tanh(C[t][nt][2*h+0] + b0));
                    smf[SBUFA + r*ST + PERM(col+1)] =
                        to_tf32f(fast_tanh(C[t][nt][2*h+1] + b1));
                }
            }
    }

    // ---- GEMM R: bufB(y_j) @ Wr^T -> actR back into bufB ----
    {
        float C[2][4][4];
#pragma unroll
        for (int t=0;t<2;++t)
#pragma unroll
            for (int nt=0;nt<4;++nt)
#pragma unroll
                for (int q=0;q<4;++q) C[t][nt][q] = 0.f;
        gemm32p(smf + SBUFB, rowbase, smf + SWR, C, g, tig);
        __syncwarp();
#pragma unroll
        for (int t=0;t<2;++t)
#pragma unroll
            for (int nt=0;nt<4;++nt) {
                int col = nt*8 + 2*tig;
                float b0 = smf[SBR+col], b1 = smf[SBR+col+1];
#pragma unroll
                for (int h=0;h<2;++h) {
                    int r = rowbase + 16*t + g + 8*h;
                    smf[SBUFB + r*ST + PERM(col)]   =
                        to_tf32f(fast_tanh(C[t][nt][2*h+0] + b0));
                    smf[SBUFB + r*ST + PERM(col+1)] =
                        to_tf32f(fast_tanh(C[t][nt][2*h+1] + b1));
                }
            }
    }
    __syncwarp();

    // ---- GEMM O = actA @ El^T + actR @ Elr^T ----
    float CO[2][4][4];
#pragma unroll
    for (int t=0;t<2;++t)
#pragma unroll
        for (int nt=0;nt<4;++nt)
#pragma unroll
            for (int q=0;q<4;++q) CO[t][nt][q] = 0.f;
    gemm32p(smf + SBUFA, rowbase, smf + SEL,  CO, g, tig);
    gemm32p(smf + SBUFB, rowbase, smf + SELR, CO, g, tig);

    // ---- integrate + store; |act| reloaded from smem (tf32) ----
#pragma unroll
    for (int t=0;t<2;++t)
#pragma unroll
        for (int nt=0;nt<4;++nt) {
            int col = nt*8 + 2*tig;
            float s0 = smf[SSIT+col], s1 = smf[SSIT+col+1];
            int p0 = PERM(col), p1 = PERM(col+1);
#pragma unroll
            for (int h=0;h<2;++h) {
                int r = rowbase + 16*t + g + 8*h;
                float2 yv = *reinterpret_cast<const float2*>(
                    ysl + (size_t)r*NSTATE + col);
                float a0 = fabsf(smf[SBUFA + r*ST + p0]);
                float a1 = fabsf(smf[SBUFA + r*ST + p1]);
                float rb0 = fabsf(smf[SBUFB + r*ST + p0]);
                float rb1 = fabsf(smf[SBUFB + r*ST + p1]);
                float d0 = s0 + a0 + rb0;
                float d1 = s1 + a1 + rb1;
                float y0 = fmaf(DT_C, CO[t][nt][2*h+0] - yv.x*d0, yv.x);
                float y1 = fmaf(DT_C, CO[t][nt][2*h+1] - yv.y*d1, yv.y);
                *reinterpret_cast<float2*>(odl + (size_t)r*NSTATE + col) =
                    make_float2(y0, y1);
            }
        }
}

extern "C" void kernel_launch(void* const* d_in, const int* in_sizes, int n_in,
                              void* d_out, int out_size)
{
    const float* y     = (const float*)d_in[0];
    const float* u_t   = (const float*)d_in[1];
    const float* W_in  = (const float*)d_in[2];
    const float* b_in  = (const float*)d_in[3];
    const float* W_fwd = (const float*)d_in[4];
    const float* b_fwd = (const float*)d_in[5];
    const float* W_rec = (const float*)d_in[6];
    const float* b_rec = (const float*)d_in[7];
    const float* E_l   = (const float*)d_in[8];
    const float* E_lr  = (const float*)d_in[9];
    const float* tau   = (const float*)d_in[10];
    const int*   nst   = (const int*)d_in[11];
    float* out = (float*)d_out;

    float *buf0, *buf1;
    cudaGetSymbolAddress((void**)&buf0, g_buf0);
    cudaGetSymbolAddress((void**)&buf1, g_buf1);

    cudaFuncSetAttribute(ltcn_step_mma,
                         cudaFuncAttributeMaxDynamicSharedMemorySize, SMEM_BYTES);

    ltcn_precompute<<<BATCH/PTPB, PTPB>>>(u_t, W_in, b_in);

    dim3 grid(BATCH/MTILE, NBLK);
    for (int s = 0; s < 8; ++s) {
        const float* srcp = (s == 0) ? y   : ((s & 1) ? buf0 : buf1);
        float*       dstp = (s == 7) ? out : ((s & 1) ? buf1 : buf0);
        ltcn_step_mma<<<grid, TPB, SMEM_BYTES>>>(srcp, dstp, W_fwd, b_fwd,
                                                 W_rec, b_rec, E_l, E_lr,
                                                 tau, nst, s);
    }
}

// round 16
// speedup vs baseline: 1.3694x; 1.3694x over previous
#include <cuda_runtime.h>
#include <cstdint>
#include <math.h>

#define BATCH   32768
#define NBLK    16
#define KD      32
#define NSTATE  (NBLK*KD)    // 512
#define INDIM   64
#define DT_C    0.05f
#define TAU_EPS 1e-6f
#define MTILE   128
#define TPB     128
#define PTPB    256

// smem float offsets
#define ST      36                   // permuted tile row stride
#define STY     36                   // fp32 y buffer row stride (16B-aligned rows)
#define SBUFA   0                    // y_{j-1}/net0 -> actA (128x36, permuted tf32)
#define SBUFB   (SBUFA + 128*ST)     // y_j -> actR          (128x36, permuted tf32)
#define SYB     (SBUFB + 128*ST)     // y_j fp32             (128x36)
#define SWF     (SYB  + 128*STY)     // weights 32x36 each (permuted tf32)
#define SWR     (SWF  + 32*ST)
#define SEL     (SWR  + 32*ST)
#define SELR    (SEL  + 32*ST)
#define SBF     (SELR + 32*ST)
#define SBR     (SBF + 32)
#define SSIT    (SBR + 32)
#define SM_FLOATS (SSIT + 32)
#define SMEM_BYTES (SM_FLOATS*4)

// K-column permutation: col c -> ((c&3)<<3)+((c>>3)<<1)+((c>>2)&1); for c=4q+r this is 8r+q
#define PERM(c) ((((c)&3)<<3) + (((c)>>3)<<1) + (((c)>>2)&1))

__device__ float g_buf0[BATCH*NSTATE];
__device__ float g_buf1[BATCH*NSTATE];
__device__ float g_net0[BATCH*KD];

__device__ __forceinline__ float fast_tanh(float x) {
    float r; asm("tanh.approx.f32 %0, %1;" : "=f"(r) : "f"(x)); return r;
}
__device__ __forceinline__ float to_tf32f(float f) {
    uint32_t r; asm("cvt.rna.tf32.f32 %0, %1;" : "=r"(r) : "f"(f));
    return __uint_as_float(r);
}
__device__ __forceinline__ void mma8(float c[4], float a0, float a1, float a2,
                                     float a3, float b0, float b1) {
    asm volatile(
        "mma.sync.aligned.m16n8k8.row.col.f32.tf32.tf32.f32 "
        "{%0,%1,%2,%3}, {%4,%5,%6,%7}, {%8,%9}, {%0,%1,%2,%3};"
        : "+f"(c[0]), "+f"(c[1]), "+f"(c[2]), "+f"(c[3])
        : "r"(__float_as_uint(a0)), "r"(__float_as_uint(a1)),
          "r"(__float_as_uint(a2)), "r"(__float_as_uint(a3)),
          "r"(__float_as_uint(b0)), "r"(__float_as_uint(b1)));
}

// C[2][4][4] += A(rows rowbase..+31, permuted) @ W^T (permuted)
__device__ __forceinline__ void gemm32p(const float* __restrict__ sA, int rowbase,
                                        const float* __restrict__ sW,
                                        float C[2][4][4], int g, int tig) {
    float B[4][8];
#pragma unroll
    for (int nt = 0; nt < 4; ++nt) {
        const float4* wr = reinterpret_cast<const float4*>(sW + (nt*8+g)*ST + tig*8);
        float4 w0 = wr[0], w1 = wr[1];
        B[nt][0]=w0.x; B[nt][1]=w0.y; B[nt][2]=w0.z; B[nt][3]=w0.w;
        B[nt][4]=w1.x; B[nt][5]=w1.y; B[nt][6]=w1.z; B[nt][7]=w1.w;
    }
#pragma unroll
    for (int t = 0; t < 2; ++t) {
        int rb = rowbase + 16*t;
        const float4* al = reinterpret_cast<const float4*>(sA + (rb+g)*ST + tig*8);
        const float4* ah = reinterpret_cast<const float4*>(sA + (rb+g+8)*ST + tig*8);
        float4 l0 = al[0], l1 = al[1], h0 = ah[0], h1 = ah[1];
        float lo[8] = {l0.x,l0.y,l0.z,l0.w,l1.x,l1.y,l1.z,l1.w};
        float hi[8] = {h0.x,h0.y,h0.z,h0.w,h1.x,h1.y,h1.z,h1.w};
#pragma unroll
        for (int ks = 0; ks < 4; ++ks)
#pragma unroll
            for (int nt = 0; nt < 4; ++nt)
                mma8(C[t][nt], lo[2*ks], hi[2*ks], lo[2*ks+1], hi[2*ks+1],
                     B[nt][2*ks], B[nt][2*ks+1]);
    }
}

// ---------------- Kernel A: net0 precompute ----------------
__global__ __launch_bounds__(PTPB) void ltcn_precompute(
    const float* __restrict__ u_t, const float* __restrict__ W_in,
    const float* __restrict__ b_in)
{
    __shared__ __align__(16) float sWin[KD*INDIM];
    __shared__ float sbin[KD];
    int tid = threadIdx.x;
    for (int i = tid; i < KD*INDIM; i += PTPB) sWin[i] = W_in[i];
    if (tid < KD) sbin[tid] = b_in[tid];
    __syncthreads();

    int b = blockIdx.x * PTPB + tid;
    if (b >= BATCH) return;

    float u[INDIM];
    const float4* up = reinterpret_cast<const float4*>(u_t + (size_t)b * INDIM);
#pragma unroll
    for (int i = 0; i < INDIM/4; ++i) {
        float4 t = up[i];
        u[4*i+0]=t.x; u[4*i+1]=t.y; u[4*i+2]=t.z; u[4*i+3]=t.w;
    }
    float n0[KD];
#pragma unroll 4
    for (int l = 0; l < KD; ++l) {
        float acc = sbin[l];
        const float4* wr = reinterpret_cast<const float4*>(sWin + l*INDIM);
#pragma unroll
        for (int i = 0; i < INDIM/4; ++i) {
            float4 w = wr[i];
            acc = fmaf(w.x, u[4*i+0], acc);
            acc = fmaf(w.y, u[4*i+1], acc);
            acc = fmaf(w.z, u[4*i+2], acc);
            acc = fmaf(w.w, u[4*i+3], acc);
        }
        n0[l] = fast_tanh(acc);
    }
    float4* op = reinterpret_cast<float4*>(g_net0 + (size_t)b * KD);
#pragma unroll
    for (int i = 0; i < 8; ++i)
        op[i] = make_float4(n0[4*i], n0[4*i+1], n0[4*i+2], n0[4*i+3]);
}

// ---------------- Step kernel ----------------
__global__ __launch_bounds__(TPB, 3) void ltcn_step_mma(
    const float* __restrict__ src, float* __restrict__ dst,
    const float* __restrict__ W_fwd, const float* __restrict__ b_fwd,
    const float* __restrict__ W_rec, const float* __restrict__ b_rec,
    const float* __restrict__ E_l,   const float* __restrict__ E_lr,
    const float* __restrict__ tau_raw, const int* __restrict__ n_steps, int s)
{
    extern __shared__ __align__(16) float smf[];
    const int tid  = threadIdx.x;
    const int wid  = tid >> 5;
    const int lane = tid & 31;
    const int g    = lane >> 2;
    const int tig  = lane & 3;
    const int j    = blockIdx.y;
    const int gRow = blockIdx.x * MTILE;

    const float* ysl = src + (size_t)gRow*NSTATE + (size_t)j*KD;
    float*       odl = dst + (size_t)gRow*NSTATE + (size_t)j*KD;

    // i-loop decomposition: i = tid + it*TPB; row = i>>3, q = i&7 (8 lanes per row => coalesced)
    if (s >= *n_steps) {   // passthrough, coalesced
#pragma unroll
        for (int it = 0; it < 8; ++it) {
            int i = tid + it*TPB;
            int row = i >> 3, q = i & 7;
            reinterpret_cast<float4*>(odl + (size_t)row*NSTATE)[q] =
                reinterpret_cast<const float4*>(ysl + (size_t)row*NSTATE)[q];
        }
        return;
    }

    // ---- stage y_j: coalesced load, fp32 copy + permuted tf32 (4x scalar STS transpose) ----
#pragma unroll
    for (int it = 0; it < 8; ++it) {
        int i = tid + it*TPB;
        int row = i >> 3, q = i & 7;
        float4 v = reinterpret_cast<const float4*>(ysl + (size_t)row*NSTATE)[q];
        reinterpret_cast<float4*>(smf + SYB + row*STY)[q] = v;
        float* d = smf + SBUFB + row*ST + q;
        d[0]  = to_tf32f(v.x);
        d[8]  = to_tf32f(v.y);
        d[16] = to_tf32f(v.z);
        d[24] = to_tf32f(v.w);
    }
    // ---- stage y_{j-1} or net0 into bufA (coalesced + transpose) ----
    {
        const float* asrc = (j > 0)
            ? (src + (size_t)gRow*NSTATE + (size_t)(j-1)*KD)
            : nullptr;
#pragma unroll
        for (int it = 0; it < 8; ++it) {
            int i = tid + it*TPB;
            int row = i >> 3, q = i & 7;
            float4 v = (j > 0)
                ? reinterpret_cast<const float4*>(asrc + (size_t)row*NSTATE)[q]
                : reinterpret_cast<const float4*>(g_net0 + (size_t)(gRow+row)*KD)[q];
            float* d = smf + SBUFA + row*ST + q;
            d[0]  = to_tf32f(v.x);
            d[8]  = to_tf32f(v.y);
            d[16] = to_tf32f(v.z);
            d[24] = to_tf32f(v.w);
        }
    }
    // ---- stage weights: coalesced (2 float4 per thread per matrix) + transpose ----
    {
        const float* wsrcs[4] = {
            (j > 0) ? (W_fwd + (size_t)(j-1)*KD*KD) : nullptr,
            W_rec + (size_t)j*KD*KD,
            E_l   + (size_t)j*KD*KD,
            E_lr  + (size_t)j*KD*KD };
        const int wdsts[4] = { SWF, SWR, SEL, SELR };
#pragma unroll
        for (int m = 0; m < 4; ++m) {
            if (!wsrcs[m]) continue;
#pragma unroll
            for (int it = 0; it < 2; ++it) {
                int i = tid + it*TPB;
                int row = i >> 3, q = i & 7;
                float4 v = reinterpret_cast<const float4*>(wsrcs[m])[i];
                float* d = smf + wdsts[m] + row*ST + q;
                d[0]  = to_tf32f(v.x);
                d[8]  = to_tf32f(v.y);
                d[16] = to_tf32f(v.z);
                d[24] = to_tf32f(v.w);
            }
        }
    }
    if (tid < KD) {
        smf[SBR + tid] = b_rec[j*KD + tid];
        if (j > 0) smf[SBF + tid] = b_fwd[(j-1)*KD + tid];
        float t  = tau_raw[j*KD + tid];
        float sp = (t > 20.f) ? t : log1pf(expf(t));
        smf[SSIT + tid] = 1.0f / (sp + TAU_EPS);
    }
    __syncthreads();

    const int rowbase = wid * 32;
    float aabs[2][4][4], rabs[2][4][4];

    // ---- GEMM P (j>0): bufA @ Wf^T -> actA (in-place) ----
    if (j > 0) {
        float C[2][4][4];
#pragma unroll
        for (int t=0;t<2;++t)
#pragma unroll
            for (int nt=0;nt<4;++nt)
#pragma unroll
                for (int q=0;q<4;++q) C[t][nt][q] = 0.f;
        gemm32p(smf + SBUFA, rowbase, smf + SWF, C, g, tig);
        __syncwarp();
#pragma unroll
        for (int t=0;t<2;++t)
#pragma unroll
            for (int nt=0;nt<4;++nt) {
                int col = nt*8 + 2*tig;
                float b0 = smf[SBF+col], b1 = smf[SBF+col+1];
#pragma unroll
                for (int h=0;h<2;++h) {
                    int r = rowbase + 16*t + g + 8*h;
                    float a0 = fast_tanh(C[t][nt][2*h+0] + b0);
                    float a1 = fast_tanh(C[t][nt][2*h+1] + b1);
                    aabs[t][nt][2*h+0] = fabsf(a0);
                    aabs[t][nt][2*h+1] = fabsf(a1);
                    smf[SBUFA + r*ST + PERM(col)]   = to_tf32f(a0);
                    smf[SBUFA + r*ST + PERM(col+1)] = to_tf32f(a1);
                }
            }
    } else {
        // |net0| from permuted bufA (tf32 |.|; negligible vs fp32)
#pragma unroll
        for (int t=0;t<2;++t)
#pragma unroll
            for (int nt=0;nt<4;++nt) {
                int col = nt*8 + 2*tig;
                int p0 = PERM(col), p1 = PERM(col+1);
#pragma unroll
                for (int h=0;h<2;++h) {
                    int r = rowbase + 16*t + g + 8*h;
                    aabs[t][nt][2*h+0] = fabsf(smf[SBUFA + r*ST + p0]);
                    aabs[t][nt][2*h+1] = fabsf(smf[SBUFA + r*ST + p1]);
                }
            }
    }

    // ---- GEMM R: bufB @ Wr^T -> actR (in-place) ----
    {
        float C[2][4][4];
#pragma unroll
        for (int t=0;t<2;++t)
#pragma unroll
            for (int nt=0;nt<4;++nt)
#pragma unroll
                for (int q=0;q<4;++q) C[t][nt][q] = 0.f;
        gemm32p(smf + SBUFB, rowbase, smf + SWR, C, g, tig);
        __syncwarp();
#pragma unroll
        for (int t=0;t<2;++t)
#pragma unroll
            for (int nt=0;nt<4;++nt) {
                int col = nt*8 + 2*tig;
                float b0 = smf[SBR+col], b1 = smf[SBR+col+1];
#pragma unroll
                for (int h=0;h<2;++h) {
                    int r = rowbase + 16*t + g + 8*h;
                    float a0 = fast_tanh(C[t][nt][2*h+0] + b0);
                    float a1 = fast_tanh(C[t][nt][2*h+1] + b1);
                    rabs[t][nt][2*h+0] = fabsf(a0);
                    rabs[t][nt][2*h+1] = fabsf(a1);
                    smf[SBUFB + r*ST + PERM(col)]   = to_tf32f(a0);
                    smf[SBUFB + r*ST + PERM(col+1)] = to_tf32f(a1);
                }
            }
    }
    __syncwarp();

    // ---- GEMM O = actA @ El^T + actR @ Elr^T ----
    float CO[2][4][4];
#pragma unroll
    for (int t=0;t<2;++t)
#pragma unroll
        for (int nt=0;nt<4;++nt)
#pragma unroll
            for (int q=0;q<4;++q) CO[t][nt][q] = 0.f;
    gemm32p(smf + SBUFA, rowbase, smf + SEL,  CO, g, tig);
    gemm32p(smf + SBUFB, rowbase, smf + SELR, CO, g, tig);

    // ---- integrate in C layout against fp32 smem y; write back to ybuf ----
#pragma unroll
    for (int t=0;t<2;++t)
#pragma unroll
        for (int nt=0;nt<4;++nt) {
            int col = nt*8 + 2*tig;
            float s0 = smf[SSIT+col], s1 = smf[SSIT+col+1];
#pragma unroll
            for (int h=0;h<2;++h) {
                int r = rowbase + 16*t + g + 8*h;
                float* yp = smf + SYB + r*STY + col;
                float yv0 = yp[0], yv1 = yp[1];
                float d0 = s0 + aabs[t][nt][2*h+0] + rabs[t][nt][2*h+0];
                float d1 = s1 + aabs[t][nt][2*h+1] + rabs[t][nt][2*h+1];
                yp[0] = fmaf(DT_C, CO[t][nt][2*h+0] - yv0*d0, yv0);
                yp[1] = fmaf(DT_C, CO[t][nt][2*h+1] - yv1*d1, yv1);
            }
        }
    __syncthreads();

    // ---- coalesced writeout ----
#pragma unroll
    for (int it = 0; it < 8; ++it) {
        int i = tid + it*TPB;
        int row = i >> 3, q = i & 7;
        reinterpret_cast<float4*>(odl + (size_t)row*NSTATE)[q] =
            reinterpret_cast<const float4*>(smf + SYB + row*STY)[q];
    }
}

extern "C" void kernel_launch(void* const* d_in, const int* in_sizes, int n_in,
                              void* d_out, int out_size)
{
    const float* y     = (const float*)d_in[0];
    const float* u_t   = (const float*)d_in[1];
    const float* W_in  = (const float*)d_in[2];
    const float* b_in  = (const float*)d_in[3];
    const float* W_fwd = (const float*)d_in[4];
    const float* b_fwd = (const float*)d_in[5];
    const float* W_rec = (const float*)d_in[6];
    const float* b_rec = (const float*)d_in[7];
    const float* E_l   = (const float*)d_in[8];
    const float* E_lr  = (const float*)d_in[9];
    const float* tau   = (const float*)d_in[10];
    const int*   nst   = (const int*)d_in[11];
    float* out = (float*)d_out;

    float *buf0, *buf1;
    cudaGetSymbolAddress((void**)&buf0, g_buf0);
    cudaGetSymbolAddress((void**)&buf1, g_buf1);

    cudaFuncSetAttribute(ltcn_step_mma,
                         cudaFuncAttributeMaxDynamicSharedMemorySize, SMEM_BYTES);

    ltcn_precompute<<<BATCH/PTPB, PTPB>>>(u_t, W_in, b_in);

    dim3 grid(BATCH/MTILE, NBLK);
    for (int s = 0; s < 8; ++s) {
        const float* srcp = (s == 0) ? y   : ((s & 1) ? buf0 : buf1);
        float*       dstp = (s == 7) ? out : ((s & 1) ? buf1 : buf0);
        ltcn_step_mma<<<grid, TPB, SMEM_BYTES>>>(srcp, dstp, W_fwd, b_fwd,
                                                 W_rec, b_rec, E_l, E_lr,
                                                 tau, nst, s);
    }
}

// round 17
// speedup vs baseline: 1.9908x; 1.4537x over previous
#include <cuda_runtime.h>
#include <cuda_fp16.h>
#include <cstdint>
#include <math.h>

#define BATCH   32768
#define NBLK    16
#define KD      32
#define NSTATE  (NBLK*KD)    // 512
#define INDIM   64
#define DT_C    0.05f
#define TAU_EPS 1e-6f
#define MTILE   128
#define TPB     128
#define PTPB    256

// ---- smem word (b32) offsets ----
#define STB   20                     // b32 stride of fp16-pair tiles (conflict-free for LDSM)
#define STY   36                     // fp32 y tile stride (floats)
#define SBUFA 0                      // 128 x STB  (fp16 pairs): y_{j-1}/net0 -> actA
#define SBUFB (SBUFA + 128*STB)      // 128 x STB: y_j -> actR
#define SWF   (SBUFB + 128*STB)      // 32 x STB each
#define SWR   (SWF + 32*STB)
#define SEL   (SWR + 32*STB)
#define SELR  (SEL + 32*STB)
#define SYB   (SELR + 32*STB)        // fp32 y, 128 x STY
#define SBF   (SYB + 128*STY)
#define SBR   (SBF + 32)
#define SSIT  (SBR + 32)
#define SM_WORDS (SSIT + 32)
#define SMEM_BYTES (SM_WORDS*4)

__device__ float g_buf0[BATCH*NSTATE];
__device__ float g_buf1[BATCH*NSTATE];
__device__ float g_net0[BATCH*KD];

__device__ __forceinline__ float fast_tanh(float x) {
    float r; asm("tanh.approx.f32 %0, %1;" : "=f"(r) : "f"(x)); return r;
}
// pack two f32 -> f16x2 {lo, hi}
__device__ __forceinline__ uint32_t pack_h2(float lo, float hi) {
    uint32_t d; asm("cvt.rn.f16x2.f32 %0, %1, %2;" : "=r"(d) : "f"(hi), "f"(lo));
    return d;
}
__device__ __forceinline__ void habs2(uint32_t p, float& x, float& y) {
    __half2 h = *reinterpret_cast<__half2*>(&p);
    float2 f = __half22float2(h);
    x = fabsf(f.x); y = fabsf(f.y);
}
__device__ __forceinline__ void mma16(float c[4], const uint32_t a[4],
                                      uint32_t b0, uint32_t b1) {
    asm volatile(
        "mma.sync.aligned.m16n8k16.row.col.f32.f16.f16.f32 "
        "{%0,%1,%2,%3}, {%4,%5,%6,%7}, {%8,%9}, {%0,%1,%2,%3};"
        : "+f"(c[0]), "+f"(c[1]), "+f"(c[2]), "+f"(c[3])
        : "r"(a[0]), "r"(a[1]), "r"(a[2]), "r"(a[3]), "r"(b0), "r"(b1));
}
__device__ __forceinline__ void ldsm4(uint32_t a[4], const uint32_t* p) {
    uint32_t sa = (uint32_t)__cvta_generic_to_shared(p);
    asm volatile("ldmatrix.sync.aligned.m8n8.x4.shared.b16 {%0,%1,%2,%3}, [%4];"
                 : "=r"(a[0]), "=r"(a[1]), "=r"(a[2]), "=r"(a[3]) : "r"(sa));
}

// C[2][4][4] += A(rows rowbase..+31 of tile at abase) @ W^T (wbase); fp16, K=32
__device__ __forceinline__ void gemm32h(const uint32_t* __restrict__ smu,
                                        int abase, int rowbase, int wbase,
                                        float C[2][4][4], int lane) {
    const int g = lane >> 2, tig = lane & 3;
    uint32_t B[4][2][2];
#pragma unroll
    for (int nt = 0; nt < 4; ++nt)
#pragma unroll
        for (int kc = 0; kc < 2; ++kc) {
            const uint32_t* wr = smu + wbase + (nt*8 + g)*STB + kc*8;
            B[nt][kc][0] = wr[tig];
            B[nt][kc][1] = wr[tig + 4];
        }
    // ldmatrix lane addressing: lanes 0-7 tile0 rows, 8-15 tile1(+8 rows),
    // 16-23 tile2(+4 pairs), 24-31 tile3(+8 rows,+4 pairs)
    const int rowoff = (lane & 7) + ((lane >> 3) & 1) * 8;
    const int coloff = ((lane >> 4) & 1) * 4;
#pragma unroll
    for (int t = 0; t < 2; ++t) {
#pragma unroll
        for (int kc = 0; kc < 2; ++kc) {
            uint32_t a[4];
            ldsm4(a, smu + abase + (rowbase + 16*t + rowoff)*STB + kc*8 + coloff);
#pragma unroll
            for (int nt = 0; nt < 4; ++nt)
                mma16(C[t][nt], a, B[nt][kc][0], B[nt][kc][1]);
        }
    }
}

// ---------------- Kernel A: net0 precompute ----------------
__global__ __launch_bounds__(PTPB) void ltcn_precompute(
    const float* __restrict__ u_t, const float* __restrict__ W_in,
    const float* __restrict__ b_in)
{
    __shared__ __align__(16) float sWin[KD*INDIM];
    __shared__ float sbin[KD];
    int tid = threadIdx.x;
    for (int i = tid; i < KD*INDIM; i += PTPB) sWin[i] = W_in[i];
    if (tid < KD) sbin[tid] = b_in[tid];
    __syncthreads();

    int b = blockIdx.x * PTPB + tid;
    if (b >= BATCH) return;

    float u[INDIM];
    const float4* up = reinterpret_cast<const float4*>(u_t + (size_t)b * INDIM);
#pragma unroll
    for (int i = 0; i < INDIM/4; ++i) {
        float4 t = up[i];
        u[4*i+0]=t.x; u[4*i+1]=t.y; u[4*i+2]=t.z; u[4*i+3]=t.w;
    }
    float n0[KD];
#pragma unroll 4
    for (int l = 0; l < KD; ++l) {
        float acc = sbin[l];
        const float4* wr = reinterpret_cast<const float4*>(sWin + l*INDIM);
#pragma unroll
        for (int i = 0; i < INDIM/4; ++i) {
            float4 w = wr[i];
            acc = fmaf(w.x, u[4*i+0], acc);
            acc = fmaf(w.y, u[4*i+1], acc);
            acc = fmaf(w.z, u[4*i+2], acc);
            acc = fmaf(w.w, u[4*i+3], acc);
        }
        n0[l] = fast_tanh(acc);
    }
    float4* op = reinterpret_cast<float4*>(g_net0 + (size_t)b * KD);
#pragma unroll
    for (int i = 0; i < 8; ++i)
        op[i] = make_float4(n0[4*i], n0[4*i+1], n0[4*i+2], n0[4*i+3]);
}

// ---------------- Step kernel: fp16 mma ----------------
__global__ __launch_bounds__(TPB, 4) void ltcn_step_mma(
    const float* __restrict__ src, float* __restrict__ dst,
    const float* __restrict__ W_fwd, const float* __restrict__ b_fwd,
    const float* __restrict__ W_rec, const float* __restrict__ b_rec,
    const float* __restrict__ E_l,   const float* __restrict__ E_lr,
    const float* __restrict__ tau_raw, const int* __restrict__ n_steps, int s)
{
    extern __shared__ __align__(16) float smf[];
    uint32_t* smu = reinterpret_cast<uint32_t*>(smf);
    const int tid  = threadIdx.x;
    const int wid  = tid >> 5;
    const int lane = tid & 31;
    const int g    = lane >> 2;
    const int tig  = lane & 3;
    const int j    = blockIdx.y;
    const int gRow = blockIdx.x * MTILE;

    const float* ysl = src + (size_t)gRow*NSTATE + (size_t)j*KD;
    float*       odl = dst + (size_t)gRow*NSTATE + (size_t)j*KD;

    if (s >= *n_steps) {   // passthrough, coalesced
#pragma unroll
        for (int it = 0; it < 8; ++it) {
            int i = tid + it*TPB;
            int row = i >> 3, q = i & 7;
            reinterpret_cast<float4*>(odl + (size_t)row*NSTATE)[q] =
                reinterpret_cast<const float4*>(ysl + (size_t)row*NSTATE)[q];
        }
        return;
    }

    // ---- stage y_j: coalesced; fp32 copy + fp16 pairs (row-major) ----
#pragma unroll
    for (int it = 0; it < 8; ++it) {
        int i = tid + it*TPB;
        int row = i >> 3, q = i & 7;
        float4 v = reinterpret_cast<const float4*>(ysl + (size_t)row*NSTATE)[q];
        reinterpret_cast<float4*>(smf + SYB + row*STY)[q] = v;
        smu[SBUFB + row*STB + 2*q + 0] = pack_h2(v.x, v.y);
        smu[SBUFB + row*STB + 2*q + 1] = pack_h2(v.z, v.w);
    }
    // ---- stage y_{j-1} or net0 into bufA ----
    {
        const float* asrc = (j > 0)
            ? (src + (size_t)gRow*NSTATE + (size_t)(j-1)*KD) : nullptr;
#pragma unroll
        for (int it = 0; it < 8; ++it) {
            int i = tid + it*TPB;
            int row = i >> 3, q = i & 7;
            float4 v = (j > 0)
                ? reinterpret_cast<const float4*>(asrc + (size_t)row*NSTATE)[q]
                : reinterpret_cast<const float4*>(g_net0 + (size_t)(gRow+row)*KD)[q];
            smu[SBUFA + row*STB + 2*q + 0] = pack_h2(v.x, v.y);
            smu[SBUFA + row*STB + 2*q + 1] = pack_h2(v.z, v.w);
        }
    }
    // ---- stage weights (fp16 pairs, row-major) ----
    {
        const float* wsrcs[4] = {
            (j > 0) ? (W_fwd + (size_t)(j-1)*KD*KD) : nullptr,
            W_rec + (size_t)j*KD*KD,
            E_l   + (size_t)j*KD*KD,
            E_lr  + (size_t)j*KD*KD };
        const int wdsts[4] = { SWF, SWR, SEL, SELR };
#pragma unroll
        for (int m = 0; m < 4; ++m) {
            if (!wsrcs[m]) continue;
#pragma unroll
            for (int it = 0; it < 2; ++it) {
                int i = tid + it*TPB;
                int row = i >> 3, q = i & 7;
                float4 v = reinterpret_cast<const float4*>(wsrcs[m])[i];
                smu[wdsts[m] + row*STB + 2*q + 0] = pack_h2(v.x, v.y);
                smu[wdsts[m] + row*STB + 2*q + 1] = pack_h2(v.z, v.w);
            }
        }
    }
    if (tid < KD) {
        smf[SBR + tid] = b_rec[j*KD + tid];
        if (j > 0) smf[SBF + tid] = b_fwd[(j-1)*KD + tid];
        float t  = tau_raw[j*KD + tid];
        float sp = (t > 20.f) ? t : log1pf(expf(t));
        smf[SSIT + tid] = 1.0f / (sp + TAU_EPS);
    }
    __syncthreads();

    const int rowbase = wid * 32;
    float dacc[2][4][4];   // sit + |actA| (+ |actR| later), in C layout

    // ---- GEMM P (j>0): bufA @ Wf^T -> tanh -> actA (in-place), dacc init ----
    if (j > 0) {
        float C[2][4][4];
#pragma unroll
        for (int t=0;t<2;++t)
#pragma unroll
            for (int nt=0;nt<4;++nt)
#pragma unroll
                for (int q=0;q<4;++q) C[t][nt][q] = 0.f;
        gemm32h(smu, SBUFA, rowbase, SWF, C, lane);
        __syncwarp();
#pragma unroll
        for (int t=0;t<2;++t)
#pragma unroll
            for (int nt=0;nt<4;++nt) {
                int col = nt*8 + 2*tig;
                float b0 = smf[SBF+col], b1 = smf[SBF+col+1];
                float s0 = smf[SSIT+col], s1 = smf[SSIT+col+1];
#pragma unroll
                for (int h=0;h<2;++h) {
                    int r = rowbase + 16*t + g + 8*h;
                    float a0 = fast_tanh(C[t][nt][2*h+0] + b0);
                    float a1 = fast_tanh(C[t][nt][2*h+1] + b1);
                    dacc[t][nt][2*h+0] = s0 + fabsf(a0);
                    dacc[t][nt][2*h+1] = s1 + fabsf(a1);
                    smu[SBUFA + r*STB + nt*4 + tig] = pack_h2(a0, a1);
                }
            }
    } else {
        // dacc = sit + |net0| (read packed pairs from bufA)
#pragma unroll
        for (int t=0;t<2;++t)
#pragma unroll
            for (int nt=0;nt<4;++nt) {
                int col = nt*8 + 2*tig;
                float s0 = smf[SSIT+col], s1 = smf[SSIT+col+1];
#pragma unroll
                for (int h=0;h<2;++h) {
                    int r = rowbase + 16*t + g + 8*h;
                    float a0, a1;
                    habs2(smu[SBUFA + r*STB + nt*4 + tig], a0, a1);
                    dacc[t][nt][2*h+0] = s0 + a0;
                    dacc[t][nt][2*h+1] = s1 + a1;
                }
            }
    }

    // ---- GEMM R: bufB @ Wr^T -> tanh -> actR (in-place), dacc += |r| ----
    {
        float C[2][4][4];
#pragma unroll
        for (int t=0;t<2;++t)
#pragma unroll
            for (int nt=0;nt<4;++nt)
#pragma unroll
                for (int q=0;q<4;++q) C[t][nt][q] = 0.f;
        gemm32h(smu, SBUFB, rowbase, SWR, C, lane);
        __syncwarp();
#pragma unroll
        for (int t=0;t<2;++t)
#pragma unroll
            for (int nt=0;nt<4;++nt) {
                int col = nt*8 + 2*tig;
                float b0 = smf[SBR+col], b1 = smf[SBR+col+1];
#pragma unroll
                for (int h=0;h<2;++h) {
                    int r = rowbase + 16*t + g + 8*h;
                    float a0 = fast_tanh(C[t][nt][2*h+0] + b0);
                    float a1 = fast_tanh(C[t][nt][2*h+1] + b1);
                    dacc[t][nt][2*h+0] += fabsf(a0);
                    dacc[t][nt][2*h+1] += fabsf(a1);
                    smu[SBUFB + r*STB + nt*4 + tig] = pack_h2(a0, a1);
                }
            }
    }
    __syncwarp();

    // ---- GEMM O = actA @ El^T + actR @ Elr^T ----
    float CO[2][4][4];
#pragma unroll
    for (int t=0;t<2;++t)
#pragma unroll
        for (int nt=0;nt<4;++nt)
#pragma unroll
            for (int q=0;q<4;++q) CO[t][nt][q] = 0.f;
    gemm32h(smu, SBUFA, rowbase, SEL,  CO, lane);
    gemm32h(smu, SBUFB, rowbase, SELR, CO, lane);

    // ---- integrate in C layout against fp32 smem y ----
#pragma unroll
    for (int t=0;t<2;++t)
#pragma unroll
        for (int nt=0;nt<4;++nt) {
            int col = nt*8 + 2*tig;
#pragma unroll
            for (int h=0;h<2;++h) {
                int r = rowbase + 16*t + g + 8*h;
                float* yp = smf + SYB + r*STY + col;
                float yv0 = yp[0], yv1 = yp[1];
                yp[0] = fmaf(DT_C, CO[t][nt][2*h+0] - yv0*dacc[t][nt][2*h+0], yv0);
                yp[1] = fmaf(DT_C, CO[t][nt][2*h+1] - yv1*dacc[t][nt][2*h+1], yv1);
            }
        }
    __syncthreads();

    // ---- coalesced writeout ----
#pragma unroll
    for (int it = 0; it < 8; ++it) {
        int i = tid + it*TPB;
        int row = i >> 3, q = i & 7;
        reinterpret_cast<float4*>(odl + (size_t)row*NSTATE)[q] =
            reinterpret_cast<const float4*>(smf + SYB + row*STY)[q];
    }
}

extern "C" void kernel_launch(void* const* d_in, const int* in_sizes, int n_in,
                              void* d_out, int out_size)
{
    const float* y     = (const float*)d_in[0];
    const float* u_t   = (const float*)d_in[1];
    const float* W_in  = (const float*)d_in[2];
    const float* b_in  = (const float*)d_in[3];
    const float* W_fwd = (const float*)d_in[4];
    const float* b_fwd = (const float*)d_in[5];
    const float* W_rec = (const float*)d_in[6];
    const float* b_rec = (const float*)d_in[7];
    const float* E_l   = (const float*)d_in[8];
    const float* E_lr  = (const float*)d_in[9];
    const float* tau   = (const float*)d_in[10];
    const int*   nst   = (const int*)d_in[11];
    float* out = (float*)d_out;

    float *buf0, *buf1;
    cudaGetSymbolAddress((void**)&buf0, g_buf0);
    cudaGetSymbolAddress((void**)&buf1, g_buf1);

    cudaFuncSetAttribute(ltcn_step_mma,
                         cudaFuncAttributeMaxDynamicSharedMemorySize, SMEM_BYTES);

    ltcn_precompute<<<BATCH/PTPB, PTPB>>>(u_t, W_in, b_in);

    dim3 grid(BATCH/MTILE, NBLK);
    for (int s = 0; s < 8; ++s) {
        const float* srcp = (s == 0) ? y   : ((s & 1) ? buf0 : buf1);
        float*       dstp = (s == 7) ? out : ((s & 1) ? buf1 : buf0);
        ltcn_step_mma<<<grid, TPB, SMEM_BYTES>>>(srcp, dstp, W_fwd, b_fwd,
                                                 W_rec, b_rec, E_l, E_lr,
                                                 tau, nst, s);
    }
}